// round 1
// baseline (speedup 1.0000x reference)
#include <cuda_runtime.h>
#include <cuda_bf16.h>
#include <math.h>

// Problem constants (from reference): B=4, S=4096, H=2048, E=8, K=2
#define T_TOKENS 16384
#define HDIM     2048
#define NEXP     8
#define TOPK     2
#define H4       (HDIM / 4)   // 512 float4 per row

// Global scratch for per-expert token counts (no allocations allowed).
__device__ int g_counts[NEXP];

__global__ void zero_counts_kernel() {
    if (threadIdx.x < NEXP) g_counts[threadIdx.x] = 0;
}

// One warp processes a group of 4 tokens at a time so each gate_w load is
// amortized across 4 tokens (cuts L1 weight traffic 4x).
// Grid: 512 blocks x 256 threads = 4096 warps = exactly T/4 groups.
__global__ __launch_bounds__(256, 4)
void router_kernel(const float* __restrict__ x,
                   const float* __restrict__ gate_w,
                   float* __restrict__ out) {
    __shared__ int s_counts[NEXP];
    if (threadIdx.x < NEXP) s_counts[threadIdx.x] = 0;
    __syncthreads();

    const int lane        = threadIdx.x & 31;
    const int warp_global = (blockIdx.x * blockDim.x + threadIdx.x) >> 5;
    const int num_warps   = (gridDim.x * blockDim.x) >> 5;
    const int num_groups  = T_TOKENS / 4;

    const float4* __restrict__ x4 = (const float4*)x;
    const float4* __restrict__ w4p = (const float4*)gate_w;

    for (int g = warp_global; g < num_groups; g += num_warps) {
        const int t0 = g * 4;

        float acc[4][NEXP];
        #pragma unroll
        for (int m = 0; m < 4; m++)
            #pragma unroll
            for (int e = 0; e < NEXP; e++) acc[m][e] = 0.0f;

        // Strided over the 512 float4's of each row; 16 iterations per lane.
        #pragma unroll 4
        for (int i = lane; i < H4; i += 32) {
            float4 wv[NEXP];
            #pragma unroll
            for (int e = 0; e < NEXP; e++)
                wv[e] = __ldg(w4p + e * H4 + i);

            #pragma unroll
            for (int m = 0; m < 4; m++) {
                float4 xv = __ldg(x4 + (size_t)(t0 + m) * H4 + i);
                #pragma unroll
                for (int e = 0; e < NEXP; e++) {
                    acc[m][e] = fmaf(xv.x, wv[e].x, acc[m][e]);
                    acc[m][e] = fmaf(xv.y, wv[e].y, acc[m][e]);
                    acc[m][e] = fmaf(xv.z, wv[e].z, acc[m][e]);
                    acc[m][e] = fmaf(xv.w, wv[e].w, acc[m][e]);
                }
            }
        }

        // Butterfly-reduce all 32 accumulators across the warp.
        #pragma unroll
        for (int m = 0; m < 4; m++)
            #pragma unroll
            for (int e = 0; e < NEXP; e++)
                #pragma unroll
                for (int off = 16; off > 0; off >>= 1)
                    acc[m][e] += __shfl_xor_sync(0xFFFFFFFFu, acc[m][e], off);

        // Lanes 0..3 each finish one token (all lanes hold full sums).
        if (lane < 4) {
            const int t = t0 + lane;
            float l[NEXP];
            #pragma unroll
            for (int e = 0; e < NEXP; e++) l[e] = acc[lane][e];

            // top-1 (strict > keeps lowest index on tie, matching jax top_k)
            float m1 = l[0]; int i1 = 0;
            #pragma unroll
            for (int e = 1; e < NEXP; e++)
                if (l[e] > m1) { m1 = l[e]; i1 = e; }
            // top-2
            float m2 = -INFINITY; int i2 = 0;
            #pragma unroll
            for (int e = 0; e < NEXP; e++)
                if (e != i1 && l[e] > m2) { m2 = l[e]; i2 = e; }

            // renormalized top-2 softmax weights
            float e2 = __expf(m2 - m1);      // <= 1, numerically safe
            float inv = 1.0f / (1.0f + e2);
            float w1 = inv;
            float w2 = e2 * inv;

            out[(size_t)t * TOPK + 0] = w1;
            out[(size_t)t * TOPK + 1] = w2;
            out[(size_t)T_TOKENS * TOPK + (size_t)t * TOPK + 0] = (float)i1;
            out[(size_t)T_TOKENS * TOPK + (size_t)t * TOPK + 1] = (float)i2;

            atomicAdd(&s_counts[i1], 1);
            atomicAdd(&s_counts[i2], 1);
        }
    }

    __syncthreads();
    if (threadIdx.x < NEXP)
        atomicAdd(&g_counts[threadIdx.x], s_counts[threadIdx.x]);
}

__global__ void finalize_kernel(float* __restrict__ out) {
    if (threadIdx.x == 0) {
        float mpe[NEXP];
        float mu = 0.0f;
        #pragma unroll
        for (int e = 0; e < NEXP; e++) {
            mpe[e] = (float)g_counts[e] / (float)T_TOKENS;
            mu += mpe[e];
        }
        mu *= (1.0f / NEXP);
        float v = 0.0f;
        #pragma unroll
        for (int e = 0; e < NEXP; e++) {
            float d = mpe[e] - mu;
            v += d * d;
        }
        v *= (1.0f / (NEXP - 1));   // unbiased variance (ddof=1)
        out[(size_t)T_TOKENS * TOPK * 2] = v * (float)NEXP;
    }
}

extern "C" void kernel_launch(void* const* d_in, const int* in_sizes, int n_in,
                              void* d_out, int out_size) {
    const float* x      = (const float*)d_in[0];   // (B,S,H) = (T, H)
    const float* gate_w = (const float*)d_in[1];   // (E, H)
    float* out = (float*)d_out;

    zero_counts_kernel<<<1, 32>>>();
    router_kernel<<<512, 256>>>(x, gate_w, out);
    finalize_kernel<<<1, 32>>>(out);
}

// round 2
// speedup vs baseline: 1.9340x; 1.9340x over previous
#include <cuda_runtime.h>
#include <cuda_bf16.h>
#include <math.h>

// Problem constants: B=4, S=4096, H=2048, E=8, K=2
#define T_TOKENS 16384
#define HDIM     2048
#define NEXP     8
#define TOPK     2
#define HV       (HDIM / 4)   // 512 16-byte vectors per row

// Packed f32x2 FMA: d = a*b + d (elementwise on packed pairs). PTX-only path.
#define FMA_F32X2(d, a, b) \
    asm("fma.rn.f32x2 %0, %1, %2, %0;" : "+l"(d) : "l"(a), "l"(b))

#define UNPACK_F32X2(lo, hi, in) \
    asm("mov.b64 {%0, %1}, %2;" : "=f"(lo), "=f"(hi) : "l"(in))

// Per-expert token counts. Zero-initialized at module load; finalize_kernel
// re-zeros after each use so every graph replay sees a clean state.
__device__ int g_counts[NEXP];

// One warp processes 4 tokens; lanes split H. Packed f32x2 FMAs halve
// FMA-pipe issue. 512 blocks x 256 threads = 4096 warps = T/4 groups.
__global__ __launch_bounds__(256, 2)
void router_kernel(const float* __restrict__ x,
                   const float* __restrict__ gate_w,
                   float* __restrict__ out) {
    __shared__ int s_counts[NEXP];
    if (threadIdx.x < NEXP) s_counts[threadIdx.x] = 0;
    __syncthreads();

    const int lane        = threadIdx.x & 31;
    const int warp_global = (blockIdx.x * blockDim.x + threadIdx.x) >> 5;

    const ulonglong2* __restrict__ x2 = (const ulonglong2*)x;       // 4 floats per elem
    const ulonglong2* __restrict__ w2 = (const ulonglong2*)gate_w;

    const int t0 = warp_global * 4;   // exactly one group per warp

    // Packed accumulators: acc[m][e] holds (sum of even idx, sum of odd idx)
    unsigned long long acc[4][NEXP];
    #pragma unroll
    for (int m = 0; m < 4; m++)
        #pragma unroll
        for (int e = 0; e < NEXP; e++) acc[m][e] = 0ULL;

    #pragma unroll 2
    for (int i = lane; i < HV; i += 32) {
        ulonglong2 xv[4];
        #pragma unroll
        for (int m = 0; m < 4; m++)
            xv[m] = __ldg(x2 + (size_t)(t0 + m) * HV + i);

        #pragma unroll
        for (int e = 0; e < NEXP; e++) {
            ulonglong2 wv = __ldg(w2 + (size_t)e * HV + i);
            #pragma unroll
            for (int m = 0; m < 4; m++) {
                FMA_F32X2(acc[m][e], xv[m].x, wv.x);
                FMA_F32X2(acc[m][e], xv[m].y, wv.y);
            }
        }
    }

    // Collapse packed pairs, then butterfly-reduce across the warp.
    float r[4][NEXP];
    #pragma unroll
    for (int m = 0; m < 4; m++)
        #pragma unroll
        for (int e = 0; e < NEXP; e++) {
            float lo, hi;
            UNPACK_F32X2(lo, hi, acc[m][e]);
            r[m][e] = lo + hi;
        }

    #pragma unroll
    for (int m = 0; m < 4; m++)
        #pragma unroll
        for (int e = 0; e < NEXP; e++)
            #pragma unroll
            for (int off = 16; off > 0; off >>= 1)
                r[m][e] += __shfl_xor_sync(0xFFFFFFFFu, r[m][e], off);

    // Lanes 0..3 each finish one token (every lane holds the full sums).
    if (lane < 4) {
        const int t = t0 + lane;
        float l[NEXP];
        #pragma unroll
        for (int e = 0; e < NEXP; e++) l[e] = r[lane][e];

        // top-1 (strict > keeps lowest index on tie, matching jax top_k)
        float m1 = l[0]; int i1 = 0;
        #pragma unroll
        for (int e = 1; e < NEXP; e++)
            if (l[e] > m1) { m1 = l[e]; i1 = e; }
        // top-2
        float m2 = -INFINITY; int i2 = 0;
        #pragma unroll
        for (int e = 0; e < NEXP; e++)
            if (e != i1 && l[e] > m2) { m2 = l[e]; i2 = e; }

        // renormalized top-2 softmax weights
        float e2  = __expf(m2 - m1);        // <= 1, numerically safe
        float inv = 1.0f / (1.0f + e2);

        out[(size_t)t * TOPK + 0] = inv;
        out[(size_t)t * TOPK + 1] = e2 * inv;
        out[(size_t)T_TOKENS * TOPK + (size_t)t * TOPK + 0] = (float)i1;
        out[(size_t)T_TOKENS * TOPK + (size_t)t * TOPK + 1] = (float)i2;

        atomicAdd(&s_counts[i1], 1);
        atomicAdd(&s_counts[i2], 1);
    }

    __syncthreads();
    if (threadIdx.x < NEXP)
        atomicAdd(&g_counts[threadIdx.x], s_counts[threadIdx.x]);
}

__global__ void finalize_kernel(float* __restrict__ out) {
    if (threadIdx.x == 0) {
        float mpe[NEXP];
        float mu = 0.0f;
        #pragma unroll
        for (int e = 0; e < NEXP; e++) {
            mpe[e] = (float)g_counts[e] / (float)T_TOKENS;
            mu += mpe[e];
        }
        mu *= (1.0f / NEXP);
        float v = 0.0f;
        #pragma unroll
        for (int e = 0; e < NEXP; e++) {
            float d = mpe[e] - mu;
            v += d * d;
        }
        v *= (1.0f / (NEXP - 1));   // unbiased variance (ddof=1)
        out[(size_t)T_TOKENS * TOPK * 2] = v * (float)NEXP;

        // Reset for the next graph replay (deterministic across calls).
        #pragma unroll
        for (int e = 0; e < NEXP; e++) g_counts[e] = 0;
    }
}

extern "C" void kernel_launch(void* const* d_in, const int* in_sizes, int n_in,
                              void* d_out, int out_size) {
    const float* x      = (const float*)d_in[0];   // (B,S,H) = (T, H)
    const float* gate_w = (const float*)d_in[1];   // (E, H)
    float* out = (float*)d_out;

    router_kernel<<<512, 256>>>(x, gate_w, out);
    finalize_kernel<<<1, 32>>>(out);
}